// round 12
// baseline (speedup 1.0000x reference)
#include <cuda_runtime.h>
#include <cstdint>

// ---------------- Problem constants ----------------
#define B_   4
#define N_   6
#define D_   41
#define FH_  16
#define FW_  44
#define C_   64
#define NX0_ 200
#define NX1_ 200
#define NPTS (B_ * N_ * D_ * FH_ * FW_)        // 692736
#define SCRATCH_ELEMS ((size_t)B_ * NX0_ * NX1_ * C_)  // 10,240,000 floats (~41MB)
#define ZERO_BLOCKS 2500                       // 4 STG.128 per thread

// frustum steps (fp32 compile-time, identical to jnp.linspace's step)
#define XSTEP (703.0f / 43.0f)
#define YSTEP 17.0f

// scratch accumulator: [B, X, Y, C] channel-contiguous.
// Zeroed by the prep kernel's STG.128 sweep immediately before the splat.
// The kernel-store sweep is load-bearing: it leaves scratch L2-resident, and
// warm-line atomics are ~3x faster than cold (measured R6/R7).
__device__ float g_scratch[SCRATCH_ELEMS];

// per-(b,n) params: 24 floats = { Pinv[9], M[9] (=rots@inv(K)), post_trans[3], trans[3] }
__device__ float g_par[B_ * N_ * 24];

// 3-term dot, XLA-fusion style: separate mul + LTR add, NO fma. (Bit-matches ref.)
__device__ __forceinline__ float dot3_nofma(float a0, float b0, float a1, float b1,
                                            float a2, float b2) {
    return __fadd_rn(__fadd_rn(__fmul_rn(a0, b0), __fmul_rn(a1, b1)), __fmul_rn(a2, b2));
}

// Gauss-Jordan inverse with partial pivoting (fp32), matches jnp.linalg.inv LU path
// for these inputs. Op sequence frozen (bit-exactness validated R3..R11).
__device__ void inv3_gj(const float* A, float* out) {
    float M[3][6];
    #pragma unroll
    for (int r = 0; r < 3; r++) {
        #pragma unroll
        for (int c = 0; c < 3; c++) {
            M[r][c] = A[r * 3 + c];
            M[r][c + 3] = (r == c) ? 1.0f : 0.0f;
        }
    }
    for (int col = 0; col < 3; col++) {
        int p = col; float mx = fabsf(M[col][col]);
        for (int r = col + 1; r < 3; r++) {
            float v = fabsf(M[r][col]);
            if (v > mx) { mx = v; p = r; }
        }
        if (p != col) {
            for (int c = 0; c < 6; c++) { float t = M[col][c]; M[col][c] = M[p][c]; M[p][c] = t; }
        }
        float piv = M[col][col];
        for (int r = col + 1; r < 3; r++) {
            float f = __fdiv_rn(M[r][col], piv);
            for (int c = col; c < 6; c++) M[r][c] = __fadd_rn(M[r][c], -__fmul_rn(f, M[col][c]));
        }
    }
    for (int col = 2; col >= 0; col--) {
        for (int r = 0; r < col; r++) {
            float f = __fdiv_rn(M[r][col], M[col][col]);
            for (int c = col; c < 6; c++) M[r][c] = __fadd_rn(M[r][c], -__fmul_rn(f, M[col][c]));
        }
    }
    #pragma unroll
    for (int r = 0; r < 3; r++) {
        float piv = M[r][r];
        #pragma unroll
        for (int c = 0; c < 3; c++) out[r * 3 + c] = __fdiv_rn(M[r][c + 3], piv);
    }
}

// Fused prep: blocks [0, ZERO_BLOCKS) zero scratch (STG.128 sweep, near its
// L1TEX-wavefront floor); block ZERO_BLOCKS computes camera params.
__global__ void __launch_bounds__(256) prep_kernel(const float* __restrict__ rots,
                                                   const float* __restrict__ trans,
                                                   const float* __restrict__ intrins,
                                                   const float* __restrict__ post_rots,
                                                   const float* __restrict__ post_trans) {
    if (blockIdx.x < ZERO_BLOCKS) {
        float4* p = reinterpret_cast<float4*>(g_scratch);
        size_t n4 = SCRATCH_ELEMS / 4;               // 2,560,000
        size_t base = (size_t)blockIdx.x * 1024 + threadIdx.x;
        #pragma unroll
        for (int k = 0; k < 4; k++) {
            size_t idx = base + (size_t)k * 256;
            if (idx < n4) p[idx] = make_float4(0.f, 0.f, 0.f, 0.f);
        }
        return;
    }
    int tid = threadIdx.x;
    if (tid < B_ * N_) {
        int i = tid;
        const float* R = rots    + i * 9;
        const float* K = intrins + i * 9;
        float Kinv[9];
        inv3_gj(K, Kinv);
        float* p = g_par + i * 24;
        #pragma unroll
        for (int r = 0; r < 3; r++)
            #pragma unroll
            for (int c = 0; c < 3; c++)
                p[9 + r * 3 + c] = dot3_nofma(R[r * 3 + 0], Kinv[0 * 3 + c],
                                              R[r * 3 + 1], Kinv[1 * 3 + c],
                                              R[r * 3 + 2], Kinv[2 * 3 + c]);
    } else if (tid < 2 * B_ * N_) {
        int i = tid - B_ * N_;
        const float* PR = post_rots + i * 9;
        float Pinv[9];
        inv3_gj(PR, Pinv);
        float* p = g_par + i * 24;
        #pragma unroll
        for (int k = 0; k < 9; k++) p[k] = Pinv[k];
        #pragma unroll
        for (int k = 0; k < 3; k++) p[18 + k] = post_trans[i * 3 + k];
        #pragma unroll
        for (int k = 0; k < 3; k++) p[21 + k] = trans[i * 3 + k];
    }
}

// Splat v3: 8 points per warp (4 lanes per point), each lane handles 4 float4
// channel quads (cg, cg+4, cg+8, cg+12), all LDGs issued before all REDs
// (per-thread MLP 4). Geometry chain issues once per warp for 8 points.
__global__ void __launch_bounds__(256) splat_kernel(const float* __restrict__ x) {
    int lane = threadIdx.x & 31;
    int warp_in_grid = (blockIdx.x * blockDim.x + threadIdx.x) >> 5;
    int pt  = lane >> 2;        // which of the warp's 8 points
    int cg  = lane & 3;         // base quad index; handles cg, cg+4, cg+8, cg+12
    int pid = warp_in_grid * 8 + pt;
    if (pid >= NPTS) return;

    // decode pid -> (b, n, d, h, w) ; layout [B,N,D,fH,fW] row-major
    int t = pid;
    int w = t % FW_;  t /= FW_;
    int h = t % FH_;  t /= FH_;
    int dd = t % D_;  t /= D_;
    int n = t % N_;
    int b = t / N_;

    const float* par = g_par + (b * N_ + n) * 24;

    float fx = __fmul_rn((float)w, XSTEP);
    float fy = __fmul_rn((float)h, YSTEP);
    float fd = 4.0f + (float)dd;   // exact integers

    float px = __fadd_rn(fx, -__ldg(&par[18]));
    float py = __fadd_rn(fy, -__ldg(&par[19]));
    float pz = __fadd_rn(fd, -__ldg(&par[20]));

    float qx = dot3_nofma(__ldg(&par[0]), px, __ldg(&par[1]), py, __ldg(&par[2]), pz);
    float qy = dot3_nofma(__ldg(&par[3]), px, __ldg(&par[4]), py, __ldg(&par[5]), pz);
    float qz = dot3_nofma(__ldg(&par[6]), px, __ldg(&par[7]), py, __ldg(&par[8]), pz);

    float rx = __fmul_rn(qx, qz), ry = __fmul_rn(qy, qz), rz = qz;

    float gx = __fadd_rn(dot3_nofma(__ldg(&par[9]),  rx, __ldg(&par[10]), ry, __ldg(&par[11]), rz), __ldg(&par[21]));
    float gy = __fadd_rn(dot3_nofma(__ldg(&par[12]), rx, __ldg(&par[13]), ry, __ldg(&par[14]), rz), __ldg(&par[22]));
    float gz = __fadd_rn(dot3_nofma(__ldg(&par[15]), rx, __ldg(&par[16]), ry, __ldg(&par[17]), rz), __ldg(&par[23]));

    // (g+50)/0.5 == (g+50)*2 bit-exactly (division by a power of two; validated R6..R11)
    float vx = __fmul_rn(__fadd_rn(gx, 50.0f), 2.0f);
    float vy = __fmul_rn(__fadd_rn(gy, 50.0f), 2.0f);
    float vz = __fdiv_rn(__fadd_rn(gz, 10.0f), 20.0f);
    vx = fminf(fmaxf(vx, -1e6f), 1e6f);
    vy = fminf(fmaxf(vy, -1e6f), 1e6f);
    vz = fminf(fmaxf(vz, -1e6f), 1e6f);
    int ix = (int)vx;   // trunc toward zero
    int iy = (int)vy;
    int iz = (int)vz;

    bool kept = (ix >= 0) && (ix < NX0_) && (iy >= 0) && (iy < NX1_) && (iz == 0);
    if (!kept) return;

    const float4* src = reinterpret_cast<const float4*>(x + (size_t)pid * C_);
    float4 v0 = __ldg(src + cg);
    float4 v1 = __ldg(src + cg + 4);
    float4 v2 = __ldg(src + cg + 8);
    float4 v3 = __ldg(src + cg + 12);

    float* dst = &g_scratch[(((size_t)b * NX0_ + ix) * NX1_ + iy) * C_];
    atomicAdd(reinterpret_cast<float4*>(dst + cg * 4), v0);
    atomicAdd(reinterpret_cast<float4*>(dst + cg * 4 + 16), v1);
    atomicAdd(reinterpret_cast<float4*>(dst + cg * 4 + 32), v2);
    atomicAdd(reinterpret_cast<float4*>(dst + cg * 4 + 48), v3);
}

// Transpose [B, X, Y, C] -> [B, C, X, Y]. Each block handles FOUR tiles
// (x = xa + k*50), 8y x 64c each, all-float4, MLP 4 per thread.
__global__ void __launch_bounds__(128) transpose_kernel(float* __restrict__ out) {
    __shared__ float tile[4][8][68];   // pad 68: 16B-aligned v4 slots
    int y0 = blockIdx.x * 8;
    int xa = blockIdx.y;               // [0,50)
    int b  = blockIdx.z;
    int tid = threadIdx.x;

    int cq = tid & 15;
    int yy = tid >> 4;
    #pragma unroll
    for (int k = 0; k < 4; k++) {
        int xx = xa + k * (NX0_ / 4);
        const float* src = g_scratch + (((size_t)b * NX0_ + xx) * NX1_ + y0) * C_;
        float4 v = *(reinterpret_cast<const float4*>(src + yy * C_) + cq);
        *reinterpret_cast<float4*>(&tile[k][yy][cq * 4]) = v;
    }
    __syncthreads();

    int c  = tid & 63;
    int yq = tid >> 6;
    #pragma unroll
    for (int k = 0; k < 4; k++) {
        int xx = xa + k * (NX0_ / 4);
        float4 o;
        o.x = tile[k][yq * 4 + 0][c];
        o.y = tile[k][yq * 4 + 1][c];
        o.z = tile[k][yq * 4 + 2][c];
        o.w = tile[k][yq * 4 + 3][c];
        *reinterpret_cast<float4*>(out + (((size_t)(b * C_ + c)) * NX0_ + xx) * NX1_ + y0 + yq * 4) = o;
    }
}

extern "C" void kernel_launch(void* const* d_in, const int* in_sizes, int n_in,
                              void* d_out, int out_size) {
    const float* x          = (const float*)d_in[0];
    const float* rots       = (const float*)d_in[1];
    const float* trans      = (const float*)d_in[2];
    const float* intrins    = (const float*)d_in[3];
    const float* post_rots  = (const float*)d_in[4];
    const float* post_trans = (const float*)d_in[5];
    float* out = (float*)d_out;

    // fused zero (L2-warming STG sweep) + camera params
    prep_kernel<<<ZERO_BLOCKS + 1, 256>>>(rots, trans, intrins, post_rots, post_trans);

    {
        // 8 points per warp, 8 warps per block -> 64 points per block
        int blocks = NPTS / 64;   // 10824, exact
        splat_kernel<<<blocks, 256>>>(x);
    }

    {
        dim3 grid(NX1_ / 8, NX0_ / 4, B_);  // (25, 50, 4)
        transpose_kernel<<<grid, 128>>>(out);
    }
}

// round 13
// speedup vs baseline: 1.0510x; 1.0510x over previous
#include <cuda_runtime.h>
#include <cstdint>

// ---------------- Problem constants ----------------
#define B_   4
#define N_   6
#define D_   41
#define FH_  16
#define FW_  44
#define C_   64
#define NX0_ 200
#define NX1_ 200
#define NPTS (B_ * N_ * D_ * FH_ * FW_)        // 692736
#define SCRATCH_ELEMS ((size_t)B_ * NX0_ * NX1_ * C_)  // 10,240,000 floats (~41MB)
#define ZERO_BLOCKS 2500                       // 4 STG.128 per thread

// frustum steps (fp32 compile-time, identical to jnp.linspace's step)
#define XSTEP (703.0f / 43.0f)
#define YSTEP 17.0f

// scratch accumulator: [B, X, Y, C] channel-contiguous.
// Zeroed by the prep kernel's STG.128 sweep immediately before the splat.
// The kernel-store sweep is load-bearing: it leaves scratch L2-resident, and
// warm-line atomics are ~3x faster than cold (measured R6/R7).
__device__ float g_scratch[SCRATCH_ELEMS];

// per-(b,n) params: 24 floats = { Pinv[9], M[9] (=rots@inv(K)), post_trans[3], trans[3] }
__device__ float g_par[B_ * N_ * 24];

// 3-term dot, XLA-fusion style: separate mul + LTR add, NO fma. (Bit-matches ref.)
__device__ __forceinline__ float dot3_nofma(float a0, float b0, float a1, float b1,
                                            float a2, float b2) {
    return __fadd_rn(__fadd_rn(__fmul_rn(a0, b0), __fmul_rn(a1, b1)), __fmul_rn(a2, b2));
}

// Gauss-Jordan inverse with partial pivoting (fp32), matches jnp.linalg.inv LU path
// for these inputs. Op sequence frozen (bit-exactness validated R3..R12).
__device__ void inv3_gj(const float* A, float* out) {
    float M[3][6];
    #pragma unroll
    for (int r = 0; r < 3; r++) {
        #pragma unroll
        for (int c = 0; c < 3; c++) {
            M[r][c] = A[r * 3 + c];
            M[r][c + 3] = (r == c) ? 1.0f : 0.0f;
        }
    }
    for (int col = 0; col < 3; col++) {
        int p = col; float mx = fabsf(M[col][col]);
        for (int r = col + 1; r < 3; r++) {
            float v = fabsf(M[r][col]);
            if (v > mx) { mx = v; p = r; }
        }
        if (p != col) {
            for (int c = 0; c < 6; c++) { float t = M[col][c]; M[col][c] = M[p][c]; M[p][c] = t; }
        }
        float piv = M[col][col];
        for (int r = col + 1; r < 3; r++) {
            float f = __fdiv_rn(M[r][col], piv);
            for (int c = col; c < 6; c++) M[r][c] = __fadd_rn(M[r][c], -__fmul_rn(f, M[col][c]));
        }
    }
    for (int col = 2; col >= 0; col--) {
        for (int r = 0; r < col; r++) {
            float f = __fdiv_rn(M[r][col], M[col][col]);
            for (int c = col; c < 6; c++) M[r][c] = __fadd_rn(M[r][c], -__fmul_rn(f, M[col][c]));
        }
    }
    #pragma unroll
    for (int r = 0; r < 3; r++) {
        float piv = M[r][r];
        #pragma unroll
        for (int c = 0; c < 3; c++) out[r * 3 + c] = __fdiv_rn(M[r][c + 3], piv);
    }
}

// Fused prep: blocks [0, ZERO_BLOCKS) zero scratch (STG.128 sweep);
// block ZERO_BLOCKS computes camera params (two GJ chains run concurrently).
__global__ void __launch_bounds__(256) prep_kernel(const float* __restrict__ rots,
                                                   const float* __restrict__ trans,
                                                   const float* __restrict__ intrins,
                                                   const float* __restrict__ post_rots,
                                                   const float* __restrict__ post_trans) {
    if (blockIdx.x < ZERO_BLOCKS) {
        float4* p = reinterpret_cast<float4*>(g_scratch);
        size_t n4 = SCRATCH_ELEMS / 4;               // 2,560,000
        size_t base = (size_t)blockIdx.x * 1024 + threadIdx.x;
        #pragma unroll
        for (int k = 0; k < 4; k++) {
            size_t idx = base + (size_t)k * 256;
            if (idx < n4) p[idx] = make_float4(0.f, 0.f, 0.f, 0.f);
        }
        return;
    }
    int tid = threadIdx.x;
    if (tid < B_ * N_) {
        int i = tid;
        const float* R = rots    + i * 9;
        const float* K = intrins + i * 9;
        float Kinv[9];
        inv3_gj(K, Kinv);
        float* p = g_par + i * 24;
        #pragma unroll
        for (int r = 0; r < 3; r++)
            #pragma unroll
            for (int c = 0; c < 3; c++)
                p[9 + r * 3 + c] = dot3_nofma(R[r * 3 + 0], Kinv[0 * 3 + c],
                                              R[r * 3 + 1], Kinv[1 * 3 + c],
                                              R[r * 3 + 2], Kinv[2 * 3 + c]);
    } else if (tid < 2 * B_ * N_) {
        int i = tid - B_ * N_;
        const float* PR = post_rots + i * 9;
        float Pinv[9];
        inv3_gj(PR, Pinv);
        float* p = g_par + i * 24;
        #pragma unroll
        for (int k = 0; k < 9; k++) p[k] = Pinv[k];
        #pragma unroll
        for (int k = 0; k < 3; k++) p[18 + k] = post_trans[i * 3 + k];
        #pragma unroll
        for (int k = 0; k < 3; k++) p[21 + k] = trans[i * 3 + k];
    }
}

// Splat v4: 4 points per warp (8 lanes per point), each lane handles 2 float4
// channel quads (q = cg and q = cg+8), both LDGs issued before both REDs
// (R11 memory pattern, byte-identical). NEW: the warp's 4 points are 4
// consecutive w within one (b,n,d,h) row (FW=44=11x4), so the whole row
// decode (divisions) is warp-uniform -> uniform datapath, freeing vector
// issue slots. Geometry values are bit-identical to R11.
__global__ void __launch_bounds__(256) splat_kernel(const float* __restrict__ x) {
    int lane = threadIdx.x & 31;
    int warp_in_grid = (blockIdx.x * blockDim.x + threadIdx.x) >> 5;
    int pt  = lane >> 3;        // which of the warp's 4 points (w offset)
    int cg  = lane & 7;         // quad-pair index: quads cg and cg+8

    // warp-uniform decode: warp -> (row, chunk); row -> (b, n, d, h)
    int chunk = warp_in_grid % (FW_ / 4);          // [0,11)
    int row   = warp_in_grid / (FW_ / 4);          // [0, B*N*D*FH)
    int h  = row % FH_;   int r2 = row / FH_;
    int dd = r2 % D_;     int r3 = r2 / D_;
    int n  = r3 % N_;
    int b  = r3 / N_;

    int w   = chunk * 4 + pt;                      // per-lane: uniform + pt
    int pid = row * FW_ + w;

    const float* par = g_par + (b * N_ + n) * 24;

    float fx = __fmul_rn((float)w, XSTEP);
    float fy = __fmul_rn((float)h, YSTEP);
    float fd = 4.0f + (float)dd;   // exact integers

    float px = __fadd_rn(fx, -__ldg(&par[18]));
    float py = __fadd_rn(fy, -__ldg(&par[19]));
    float pz = __fadd_rn(fd, -__ldg(&par[20]));

    float qx = dot3_nofma(__ldg(&par[0]), px, __ldg(&par[1]), py, __ldg(&par[2]), pz);
    float qy = dot3_nofma(__ldg(&par[3]), px, __ldg(&par[4]), py, __ldg(&par[5]), pz);
    float qz = dot3_nofma(__ldg(&par[6]), px, __ldg(&par[7]), py, __ldg(&par[8]), pz);

    float rx = __fmul_rn(qx, qz), ry = __fmul_rn(qy, qz), rz = qz;

    float gx = __fadd_rn(dot3_nofma(__ldg(&par[9]),  rx, __ldg(&par[10]), ry, __ldg(&par[11]), rz), __ldg(&par[21]));
    float gy = __fadd_rn(dot3_nofma(__ldg(&par[12]), rx, __ldg(&par[13]), ry, __ldg(&par[14]), rz), __ldg(&par[22]));
    float gz = __fadd_rn(dot3_nofma(__ldg(&par[15]), rx, __ldg(&par[16]), ry, __ldg(&par[17]), rz), __ldg(&par[23]));

    // (g+50)/0.5 == (g+50)*2 bit-exactly (division by a power of two; validated R6..R12)
    float vx = __fmul_rn(__fadd_rn(gx, 50.0f), 2.0f);
    float vy = __fmul_rn(__fadd_rn(gy, 50.0f), 2.0f);
    float vz = __fdiv_rn(__fadd_rn(gz, 10.0f), 20.0f);
    vx = fminf(fmaxf(vx, -1e6f), 1e6f);
    vy = fminf(fmaxf(vy, -1e6f), 1e6f);
    vz = fminf(fmaxf(vz, -1e6f), 1e6f);
    int ix = (int)vx;   // trunc toward zero
    int iy = (int)vy;
    int iz = (int)vz;

    bool kept = (ix >= 0) && (ix < NX0_) && (iy >= 0) && (iy < NX1_) && (iz == 0);
    if (!kept) return;

    const float4* src = reinterpret_cast<const float4*>(x + (size_t)pid * C_);
    float4 v0 = __ldg(src + cg);
    float4 v1 = __ldg(src + cg + 8);

    float* dst = &g_scratch[(((size_t)b * NX0_ + ix) * NX1_ + iy) * C_];
    atomicAdd(reinterpret_cast<float4*>(dst + cg * 4), v0);
    atomicAdd(reinterpret_cast<float4*>(dst + cg * 4 + 32), v1);
}

// Transpose [B, X, Y, C] -> [B, C, X, Y]. Each block handles FOUR tiles
// (x = xa + k*50), 8y x 64c each, all-float4, MLP 4 per thread.
__global__ void __launch_bounds__(128) transpose_kernel(float* __restrict__ out) {
    __shared__ float tile[4][8][68];   // pad 68: 16B-aligned v4 slots
    int y0 = blockIdx.x * 8;
    int xa = blockIdx.y;               // [0,50)
    int b  = blockIdx.z;
    int tid = threadIdx.x;

    int cq = tid & 15;
    int yy = tid >> 4;
    #pragma unroll
    for (int k = 0; k < 4; k++) {
        int xx = xa + k * (NX0_ / 4);
        const float* src = g_scratch + (((size_t)b * NX0_ + xx) * NX1_ + y0) * C_;
        float4 v = *(reinterpret_cast<const float4*>(src + yy * C_) + cq);
        *reinterpret_cast<float4*>(&tile[k][yy][cq * 4]) = v;
    }
    __syncthreads();

    int c  = tid & 63;
    int yq = tid >> 6;
    #pragma unroll
    for (int k = 0; k < 4; k++) {
        int xx = xa + k * (NX0_ / 4);
        float4 o;
        o.x = tile[k][yq * 4 + 0][c];
        o.y = tile[k][yq * 4 + 1][c];
        o.z = tile[k][yq * 4 + 2][c];
        o.w = tile[k][yq * 4 + 3][c];
        *reinterpret_cast<float4*>(out + (((size_t)(b * C_ + c)) * NX0_ + xx) * NX1_ + y0 + yq * 4) = o;
    }
}

extern "C" void kernel_launch(void* const* d_in, const int* in_sizes, int n_in,
                              void* d_out, int out_size) {
    const float* x          = (const float*)d_in[0];
    const float* rots       = (const float*)d_in[1];
    const float* trans      = (const float*)d_in[2];
    const float* intrins    = (const float*)d_in[3];
    const float* post_rots  = (const float*)d_in[4];
    const float* post_trans = (const float*)d_in[5];
    float* out = (float*)d_out;

    // fused zero (L2-warming STG sweep) + camera params
    prep_kernel<<<ZERO_BLOCKS + 1, 256>>>(rots, trans, intrins, post_rots, post_trans);

    {
        // 4 points per warp, 8 warps per block -> 32 points per block
        int blocks = NPTS / 32;   // 21648, exact
        splat_kernel<<<blocks, 256>>>(x);
    }

    {
        dim3 grid(NX1_ / 8, NX0_ / 4, B_);  // (25, 50, 4)
        transpose_kernel<<<grid, 128>>>(out);
    }
}

// round 14
// speedup vs baseline: 1.0514x; 1.0004x over previous
#include <cuda_runtime.h>
#include <cstdint>

// ---------------- Problem constants ----------------
#define B_   4
#define N_   6
#define D_   41
#define FH_  16
#define FW_  44
#define C_   64
#define NX0_ 200
#define NX1_ 200
#define NPTS (B_ * N_ * D_ * FH_ * FW_)        // 692736
#define SCRATCH_ELEMS ((size_t)B_ * NX0_ * NX1_ * C_)  // 10,240,000 floats (~41MB)
#define ZERO_BLOCKS 2500                       // 4 STG.128 per thread

// frustum steps (fp32 compile-time, identical to jnp.linspace's step)
#define XSTEP (703.0f / 43.0f)
#define YSTEP 17.0f

// scratch accumulator: [B, X, Y, C] channel-contiguous.
// Zeroed by the prep kernel's STG.128 sweep; splat overlaps with it via PDL
// and synchronizes (cudaGridDependencySynchronize) before its first atomic.
// The kernel-store sweep is load-bearing: it leaves scratch L2-resident, and
// warm-line atomics are ~3x faster than cold (measured R6/R7).
__device__ float g_scratch[SCRATCH_ELEMS];

// per-(b,n) params: 24 floats = { Pinv[9], M[9] (=rots@inv(K)), post_trans[3], trans[3] }
__device__ float g_par[B_ * N_ * 24];

// 3-term dot, XLA-fusion style: separate mul + LTR add, NO fma. (Bit-matches ref.)
__device__ __forceinline__ float dot3_nofma(float a0, float b0, float a1, float b1,
                                            float a2, float b2) {
    return __fadd_rn(__fadd_rn(__fmul_rn(a0, b0), __fmul_rn(a1, b1)), __fmul_rn(a2, b2));
}

// Gauss-Jordan inverse with partial pivoting (fp32), matches jnp.linalg.inv LU path
// for these inputs. Op sequence frozen (bit-exactness validated R3..R13).
__device__ void inv3_gj(const float* A, float* out) {
    float M[3][6];
    #pragma unroll
    for (int r = 0; r < 3; r++) {
        #pragma unroll
        for (int c = 0; c < 3; c++) {
            M[r][c] = A[r * 3 + c];
            M[r][c + 3] = (r == c) ? 1.0f : 0.0f;
        }
    }
    for (int col = 0; col < 3; col++) {
        int p = col; float mx = fabsf(M[col][col]);
        for (int r = col + 1; r < 3; r++) {
            float v = fabsf(M[r][col]);
            if (v > mx) { mx = v; p = r; }
        }
        if (p != col) {
            for (int c = 0; c < 6; c++) { float t = M[col][c]; M[col][c] = M[p][c]; M[p][c] = t; }
        }
        float piv = M[col][col];
        for (int r = col + 1; r < 3; r++) {
            float f = __fdiv_rn(M[r][col], piv);
            for (int c = col; c < 6; c++) M[r][c] = __fadd_rn(M[r][c], -__fmul_rn(f, M[col][c]));
        }
    }
    for (int col = 2; col >= 0; col--) {
        for (int r = 0; r < col; r++) {
            float f = __fdiv_rn(M[r][col], M[col][col]);
            for (int c = col; c < 6; c++) M[r][c] = __fadd_rn(M[r][c], -__fmul_rn(f, M[col][c]));
        }
    }
    #pragma unroll
    for (int r = 0; r < 3; r++) {
        float piv = M[r][r];
        #pragma unroll
        for (int c = 0; c < 3; c++) out[r * 3 + c] = __fdiv_rn(M[r][c + 3], piv);
    }
}

// Fused prep: blocks [0, ZERO_BLOCKS) zero scratch (STG.128 sweep);
// block ZERO_BLOCKS computes camera params. Every block fires the PDL
// trigger at entry so the splat grid can begin its independent prelude.
__global__ void __launch_bounds__(256) prep_kernel(const float* __restrict__ rots,
                                                   const float* __restrict__ trans,
                                                   const float* __restrict__ intrins,
                                                   const float* __restrict__ post_rots,
                                                   const float* __restrict__ post_trans) {
    cudaTriggerProgrammaticLaunchCompletion();
    if (blockIdx.x < ZERO_BLOCKS) {
        float4* p = reinterpret_cast<float4*>(g_scratch);
        size_t n4 = SCRATCH_ELEMS / 4;               // 2,560,000
        size_t base = (size_t)blockIdx.x * 1024 + threadIdx.x;
        #pragma unroll
        for (int k = 0; k < 4; k++) {
            size_t idx = base + (size_t)k * 256;
            if (idx < n4) p[idx] = make_float4(0.f, 0.f, 0.f, 0.f);
        }
        return;
    }
    int tid = threadIdx.x;
    if (tid < B_ * N_) {
        int i = tid;
        const float* R = rots    + i * 9;
        const float* K = intrins + i * 9;
        float Kinv[9];
        inv3_gj(K, Kinv);
        float* p = g_par + i * 24;
        #pragma unroll
        for (int r = 0; r < 3; r++)
            #pragma unroll
            for (int c = 0; c < 3; c++)
                p[9 + r * 3 + c] = dot3_nofma(R[r * 3 + 0], Kinv[0 * 3 + c],
                                              R[r * 3 + 1], Kinv[1 * 3 + c],
                                              R[r * 3 + 2], Kinv[2 * 3 + c]);
    } else if (tid < 2 * B_ * N_) {
        int i = tid - B_ * N_;
        const float* PR = post_rots + i * 9;
        float Pinv[9];
        inv3_gj(PR, Pinv);
        float* p = g_par + i * 24;
        #pragma unroll
        for (int k = 0; k < 9; k++) p[k] = Pinv[k];
        #pragma unroll
        for (int k = 0; k < 3; k++) p[18 + k] = post_trans[i * 3 + k];
        #pragma unroll
        for (int k = 0; k < 3; k++) p[21 + k] = trans[i * 3 + k];
    }
}

// Splat v5: 4 points per warp (8 lanes per point), 2 float4 quads per lane
// (R11/R13 memory pattern, byte-identical arithmetic). Launched with PDL:
// the decode + x-LDG prelude overlaps prep; cudaGridDependencySynchronize()
// orders the REDs after prep's zero-sweep + param stores.
// NOTE: reads of g_par must also come after the sync, so ALL params are read
// post-sync (they are L2-hot by then; latency hidden by 8 resident warps).
__global__ void __launch_bounds__(256) splat_kernel(const float* __restrict__ x) {
    int lane = threadIdx.x & 31;
    int warp_in_grid = (blockIdx.x * blockDim.x + threadIdx.x) >> 5;
    int pt  = lane >> 3;        // which of the warp's 4 points (w offset)
    int cg  = lane & 7;         // quad-pair index: quads cg and cg+8

    // warp-uniform decode: warp -> (row, chunk); row -> (b, n, d, h)
    int chunk = warp_in_grid % (FW_ / 4);          // [0,11)
    int row   = warp_in_grid / (FW_ / 4);          // [0, B*N*D*FH)
    int h  = row % FH_;   int r2 = row / FH_;
    int dd = r2 % D_;     int r3 = r2 / D_;
    int n  = r3 % N_;
    int b  = r3 / N_;

    int w   = chunk * 4 + pt;                      // per-lane: uniform + pt
    int pid = row * FW_ + w;

    // --- independent prelude: issue both x loads (DRAM) before waiting ---
    const float4* src = reinterpret_cast<const float4*>(x + (size_t)pid * C_);
    float4 v0 = __ldg(src + cg);
    float4 v1 = __ldg(src + cg + 8);

    // --- wait for prep grid (params + zeroed scratch visible after this) ---
    cudaGridDependencySynchronize();

    const float* par = g_par + (b * N_ + n) * 24;

    float fx = __fmul_rn((float)w, XSTEP);
    float fy = __fmul_rn((float)h, YSTEP);
    float fd = 4.0f + (float)dd;   // exact integers

    float px = __fadd_rn(fx, -__ldg(&par[18]));
    float py = __fadd_rn(fy, -__ldg(&par[19]));
    float pz = __fadd_rn(fd, -__ldg(&par[20]));

    float qx = dot3_nofma(__ldg(&par[0]), px, __ldg(&par[1]), py, __ldg(&par[2]), pz);
    float qy = dot3_nofma(__ldg(&par[3]), px, __ldg(&par[4]), py, __ldg(&par[5]), pz);
    float qz = dot3_nofma(__ldg(&par[6]), px, __ldg(&par[7]), py, __ldg(&par[8]), pz);

    float rx = __fmul_rn(qx, qz), ry = __fmul_rn(qy, qz), rz = qz;

    float gx = __fadd_rn(dot3_nofma(__ldg(&par[9]),  rx, __ldg(&par[10]), ry, __ldg(&par[11]), rz), __ldg(&par[21]));
    float gy = __fadd_rn(dot3_nofma(__ldg(&par[12]), rx, __ldg(&par[13]), ry, __ldg(&par[14]), rz), __ldg(&par[22]));
    float gz = __fadd_rn(dot3_nofma(__ldg(&par[15]), rx, __ldg(&par[16]), ry, __ldg(&par[17]), rz), __ldg(&par[23]));

    // (g+50)/0.5 == (g+50)*2 bit-exactly (division by a power of two; validated R6..R13)
    float vx = __fmul_rn(__fadd_rn(gx, 50.0f), 2.0f);
    float vy = __fmul_rn(__fadd_rn(gy, 50.0f), 2.0f);
    float vz = __fdiv_rn(__fadd_rn(gz, 10.0f), 20.0f);
    vx = fminf(fmaxf(vx, -1e6f), 1e6f);
    vy = fminf(fmaxf(vy, -1e6f), 1e6f);
    vz = fminf(fmaxf(vz, -1e6f), 1e6f);
    int ix = (int)vx;   // trunc toward zero
    int iy = (int)vy;
    int iz = (int)vz;

    bool kept = (ix >= 0) && (ix < NX0_) && (iy >= 0) && (iy < NX1_) && (iz == 0);
    if (!kept) return;

    float* dst = &g_scratch[(((size_t)b * NX0_ + ix) * NX1_ + iy) * C_];
    atomicAdd(reinterpret_cast<float4*>(dst + cg * 4), v0);
    atomicAdd(reinterpret_cast<float4*>(dst + cg * 4 + 32), v1);
}

// Transpose [B, X, Y, C] -> [B, C, X, Y]. Each block handles FOUR tiles
// (x = xa + k*50), 8y x 64c each, all-float4, MLP 4 per thread.
__global__ void __launch_bounds__(128) transpose_kernel(float* __restrict__ out) {
    __shared__ float tile[4][8][68];   // pad 68: 16B-aligned v4 slots
    int y0 = blockIdx.x * 8;
    int xa = blockIdx.y;               // [0,50)
    int b  = blockIdx.z;
    int tid = threadIdx.x;

    int cq = tid & 15;
    int yy = tid >> 4;
    #pragma unroll
    for (int k = 0; k < 4; k++) {
        int xx = xa + k * (NX0_ / 4);
        const float* src = g_scratch + (((size_t)b * NX0_ + xx) * NX1_ + y0) * C_;
        float4 v = *(reinterpret_cast<const float4*>(src + yy * C_) + cq);
        *reinterpret_cast<float4*>(&tile[k][yy][cq * 4]) = v;
    }
    __syncthreads();

    int c  = tid & 63;
    int yq = tid >> 6;
    #pragma unroll
    for (int k = 0; k < 4; k++) {
        int xx = xa + k * (NX0_ / 4);
        float4 o;
        o.x = tile[k][yq * 4 + 0][c];
        o.y = tile[k][yq * 4 + 1][c];
        o.z = tile[k][yq * 4 + 2][c];
        o.w = tile[k][yq * 4 + 3][c];
        *reinterpret_cast<float4*>(out + (((size_t)(b * C_ + c)) * NX0_ + xx) * NX1_ + y0 + yq * 4) = o;
    }
}

extern "C" void kernel_launch(void* const* d_in, const int* in_sizes, int n_in,
                              void* d_out, int out_size) {
    const float* x          = (const float*)d_in[0];
    const float* rots       = (const float*)d_in[1];
    const float* trans      = (const float*)d_in[2];
    const float* intrins    = (const float*)d_in[3];
    const float* post_rots  = (const float*)d_in[4];
    const float* post_trans = (const float*)d_in[5];
    float* out = (float*)d_out;

    // launch 1: fused zero (L2-warming STG sweep) + camera params (PDL primary)
    prep_kernel<<<ZERO_BLOCKS + 1, 256>>>(rots, trans, intrins, post_rots, post_trans);

    // launch 2: splat as PDL secondary — prelude overlaps prep
    {
        cudaLaunchConfig_t cfg = {};
        cfg.gridDim  = dim3(NPTS / 32, 1, 1);   // 21648 blocks, 4 pts/warp
        cfg.blockDim = dim3(256, 1, 1);
        cfg.dynamicSmemBytes = 0;
        cfg.stream = 0;
        cudaLaunchAttribute attrs[1];
        attrs[0].id = cudaLaunchAttributeProgrammaticStreamSerialization;
        attrs[0].val.programmaticStreamSerializationAllowed = 1;
        cfg.attrs = attrs;
        cfg.numAttrs = 1;
        cudaLaunchKernelEx(&cfg, splat_kernel, x);
    }

    // launch 3: transpose
    {
        dim3 grid(NX1_ / 8, NX0_ / 4, B_);  // (25, 50, 4)
        transpose_kernel<<<grid, 128>>>(out);
    }
}